// round 15
// baseline (speedup 1.0000x reference)
#include <cuda_runtime.h>
#include <math.h>

#define HW    256
#define EPS   1e-9f
#define WPB   8         // warps per block -> grid 128 <= 148 SMs: single wave
#define KP    42        // v-table k range [0,41]; support caps at s=41
#define NSLOT 6         // slots per lane; 8-lane group holds all 48 slots

// FTZ fp32 ops — reference is XLA-GPU-compiled (ftz=true).
__device__ __forceinline__ float fmul_ftz(float a, float b) {
    float c; asm("mul.ftz.f32 %0, %1, %2;" : "=f"(c) : "f"(a), "f"(b)); return c;
}
__device__ __forceinline__ float fadd_ftz(float a, float b) {
    float c; asm("add.ftz.f32 %0, %1, %2;" : "=f"(c) : "f"(a), "f"(b)); return c;
}
__device__ __forceinline__ float fsub_ftz(float a, float b) {
    float c; asm("sub.ftz.f32 %0, %1, %2;" : "=f"(c) : "f"(a), "f"(b)); return c;
}
__device__ __forceinline__ float fdiv_ftz(float a, float b) {
    float c; asm("div.rn.ftz.f32 %0, %1, %2;" : "=f"(c) : "f"(a), "f"(b)); return c;
}
__device__ __forceinline__ float ffma_ftz(float a, float b, float c) {
    float d; asm("fma.rn.ftz.f32 %0, %1, %2, %3;" : "=f"(d) : "f"(a), "f"(b), "f"(c)); return d;
}
__device__ __forceinline__ float frcp_approx(float a) {
    float c; asm("rcp.approx.ftz.f32 %0, %1;" : "=f"(c) : "f"(a)); return c;
}
__device__ __forceinline__ int clampk(int k) {
    return k < 0 ? 0 : (k > KP - 1 ? KP - 1 : k);
}

// One scan step; identical op structure / bits to the verified R14 kernel.
// When is_one: u[j] == pz[j] bitwise, so the pz reduction is skipped.
__device__ __forceinline__ float scan_step(float* __restrict__ c,
                                           const float* __restrict__ v,
                                           bool is_one, int lane,
                                           float* __restrict__ pz_slot)
{
    const float SC_UP = 1.8446744073709552e19f;   // 2^64
    const float SC_DN = 5.421010862427522e-20f;   // 2^-64

    float u[NSLOT];
    float psum, nsum;

    if (is_one) {
#pragma unroll
        for (int j = 0; j < NSLOT; ++j)
            u[j] = fmul_ftz(c[j], v[j]);          // == pz[j] bitwise
        nsum = fadd_ftz(fadd_ftz(fadd_ftz(u[0], u[1]),
                                 fadd_ftz(u[2], u[3])),
                        fadd_ftz(u[4], u[5]));
#pragma unroll
        for (int off = 1; off <= 4; off <<= 1)
            nsum = fadd_ftz(nsum, __shfl_xor_sync(0xffffffffu, nsum, off));
        psum = nsum;
    } else {
        float pz[NSLOT];
#pragma unroll
        for (int j = 0; j < NSLOT; ++j) {
            pz[j] = fmul_ftz(c[j], v[j]);
            u[j]  = fmul_ftz(c[j], fsub_ftz(1.0f, v[j]));
        }
        psum = fadd_ftz(fadd_ftz(fadd_ftz(pz[0], pz[1]),
                                 fadd_ftz(pz[2], pz[3])),
                        fadd_ftz(pz[4], pz[5]));
        nsum = fadd_ftz(fadd_ftz(fadd_ftz(u[0], u[1]),
                                 fadd_ftz(u[2], u[3])),
                        fadd_ftz(u[4], u[5]));
#pragma unroll
        for (int off = 1; off <= 4; off <<= 1) {
            nsum = fadd_ftz(nsum, __shfl_xor_sync(0xffffffffu, nsum, off));
            psum = fadd_ftz(psum, __shfl_xor_sync(0xffffffffu, psum, off));
        }
    }
    if (lane == 0) *pz_slot = psum;

    // branch-free correctly-rounded division (bit-identical to div.rn.ftz
    // on this kernel's domain; verified by the ~9.77e-9 canary)
    const float norm = fmaxf(nsum, 1e-6f);
    float y = frcp_approx(norm);
    y = ffma_ftz(ffma_ftz(-norm, y, 1.0f), y, y);
#pragma unroll
    for (int j = 0; j < NSLOT; ++j) {
        const float a  = fmul_ftz(u[j], SC_UP);
        const float q0 = fmul_ftz(a, y);
        const float r  = ffma_ftz(-norm, q0, a);
        c[j] = fmul_ftz(ffma_ftz(r, y, q0), SC_DN);
    }
    return nsum;
}

extern __shared__ float smem_dyn[];

__global__ __launch_bounds__(WPB * 32, 1)     // min-blocks 1 -> no 64-reg cap
void spair_obj_kl_kernel(const float* __restrict__ z_pres,
                         const float* __restrict__ z_pres_prob,
                         float* __restrict__ out, int B)
{
    // dynamic smem carve: T[HW*KP] | pz[WPB*HW] | cd0[48] | bits[WPB*8]
    float*    s_T   = smem_dyn;
    float*    s_pz  = s_T + HW * KP;
    float*    s_cd0 = s_pz + WPB * HW;
    unsigned* s_w   = (unsigned*)(s_cd0 + 48);

    const int tid  = threadIdx.x;
    const int warp = tid >> 5;
    const int lane = tid & 31;
    const int b    = blockIdx.x * WPB + warp;

    // ---- v-table: T[i][k] = div.rn.ftz(min(k, 256-i), 256-i) via unscaled
    // Markstein (correctly rounded here: integer operands, normal results).
    for (int e = tid; e < HW * KP; e += WPB * 32) {
        const int i = e / KP, k = e - i * KP, d = HW - i;
        const float fk = (float)(k < d ? k : d), fd = (float)d;
        float y = frcp_approx(fd);
        y = ffma_ftz(ffma_ftz(-fd, y, 1.0f), y, y);
        const float q0 = fmul_ftz(fk, y);
        const float r  = ffma_ftz(-fd, q0, fk);
        s_T[e] = ffma_ftz(r, y, q0);
    }

    // ---- cd0 (warp 0; exact op order of the verified kernels) ----
    if (warp == 0) {
        const float  p_f    = 1.0f / (expf(2.0f) + 1.0f);
        const double base_d = (double)p_f;
        const double omp_d  = 1.0 - base_d;
        float c0 = (float)(omp_d * pow(base_d, (double)lane));
        float c1 = (float)(omp_d * pow(base_d, (double)(lane + 32)));
        if (fabsf(c0) < 1.17549435e-38f) c0 = 0.0f;
        if (fabsf(c1) < 1.17549435e-38f) c1 = 0.0f;
        float acc = fadd_ftz(c0, c1);
#pragma unroll
        for (int off = 16; off; off >>= 1)
            acc = fadd_ftz(acc, __shfl_xor_sync(0xffffffffu, acc, off));
        s_cd0[lane] = fdiv_ftz(c0, acc);
        if (lane + 32 < 48) s_cd0[lane + 32] = fdiv_ftz(c1, acc);
    }

    // ---- sample bits ----
    if (b < B) {
        const float* zp = z_pres + (size_t)b * HW;
        unsigned mybits = 0;
#pragma unroll
        for (int j = 0; j < 8; ++j)
            mybits |= (rintf(zp[32 * j + lane]) > 0.5f) ? (1u << j) : 0u;
#pragma unroll
        for (int j = 0; j < 8; ++j) {
            const unsigned wj = __ballot_sync(0xffffffffu, (mybits >> j) & 1u);
            if (lane == 0) s_w[warp * 8 + j] = wj;
        }
    }
    __syncthreads();
    if (b >= B) return;

    const float* pp  = z_pres_prob + (size_t)b * HW;
    float*       o   = out         + (size_t)b * HW;
    float*       pzb = s_pz + warp * HW;

    const int sbase = (lane & 7) * NSLOT;     // 8-lane group owns all 48 slots
    float c[NSLOT];
#pragma unroll
    for (int j = 0; j < NSLOT; ++j) c[j] = s_cd0[sbase + j];

    float v[NSLOT];                           // step-0 v (csf = 0)
#pragma unroll
    for (int j = 0; j < NSLOT; ++j) v[j] = s_T[clampk(sbase + j)];

    int csf = 0, i_end = HW;
    unsigned cw = 0;

#pragma unroll 1
    for (int q = 0; q < HW / 4; ++q) {
        if ((q & 7) == 0) cw = s_w[warp * 8 + (q >> 3)];

        float ns;
#pragma unroll
        for (int t = 0; t < 4; ++t) {
            const int  i      = 4 * q + t;
            const bool is_one = cw & 1;
            cw >>= 1;
            csf += is_one ? 1 : 0;            // csf for step i+1 (ALU, off-chain)

            // double-buffer prefetch of next step's v (LDS hides under chain)
            float vn[NSLOT];
            const int r = (i + 1 < HW) ? (i + 1) : (HW - 1);
#pragma unroll
            for (int j = 0; j < NSLOT; ++j)
                vn[j] = s_T[r * KP + clampk(sbase + j - csf)];

            ns = scan_step(c, v, is_one, lane, pzb + i);

#pragma unroll
            for (int j = 0; j < NSLOT; ++j) v[j] = vn[j];
        }

        // death is absorbing; zeros self-propagate within the quartet,
        // so checking only the 4th nsum is exact.
        if (ns == 0.0f) { i_end = 4 * q + 4; break; }
    }

    __syncwarp();

    // ---- epilogue: KL for all 256 steps in parallel (p_z = 0 after death) --
#pragma unroll
    for (int j = 0; j < 8; ++j) {
        const int   idx = 32 * j + lane;
        const float pzv = (idx < i_end) ? pzb[idx] : 0.0f;
        const float pr  = pp[idx];
        o[idx] = pr * (logf(pr + EPS) - logf(pzv + EPS))
               + (1.0f - pr) * (logf(1.0f - pr + EPS)
                                - logf((1.0f - pzv) + EPS));
    }
}

extern "C" void kernel_launch(void* const* d_in, const int* in_sizes, int n_in,
                              void* d_out, int out_size)
{
    const float* z_pres      = (const float*)d_in[0];
    const float* z_pres_prob = (const float*)d_in[1];
    float*       out         = (float*)d_out;

    const int B = in_sizes[0] / HW;              // 1024
    const int smem_bytes = (HW * KP + WPB * HW + 48 + WPB * 8) * 4;  // ~51.6 KB
    cudaFuncSetAttribute(spair_obj_kl_kernel,
                         cudaFuncAttributeMaxDynamicSharedMemorySize, smem_bytes);
    spair_obj_kl_kernel<<<(B + WPB - 1) / WPB, WPB * 32, smem_bytes>>>(
        z_pres, z_pres_prob, out, B);
}

// round 16
// speedup vs baseline: 1.0587x; 1.0587x over previous
#include <cuda_runtime.h>
#include <math.h>

#define HW    256
#define EPS   1e-9f
#define WPB   8         // warps per block -> grid 128 <= 148 SMs: single wave
#define KW    96        // padded v-table row stride (k index range [-41, 54])
#define KOFF  41        // column offset of k = 0
#define NSLOT 6         // slots per lane; 8-lane group holds all 48 slots

// FTZ fp32 ops — reference is XLA-GPU-compiled (ftz=true).
__device__ __forceinline__ float fmul_ftz(float a, float b) {
    float c; asm("mul.ftz.f32 %0, %1, %2;" : "=f"(c) : "f"(a), "f"(b)); return c;
}
__device__ __forceinline__ float fadd_ftz(float a, float b) {
    float c; asm("add.ftz.f32 %0, %1, %2;" : "=f"(c) : "f"(a), "f"(b)); return c;
}
__device__ __forceinline__ float fsub_ftz(float a, float b) {
    float c; asm("sub.ftz.f32 %0, %1, %2;" : "=f"(c) : "f"(a), "f"(b)); return c;
}
__device__ __forceinline__ float fdiv_ftz(float a, float b) {
    float c; asm("div.rn.ftz.f32 %0, %1, %2;" : "=f"(c) : "f"(a), "f"(b)); return c;
}
__device__ __forceinline__ float ffma_ftz(float a, float b, float c) {
    float d; asm("fma.rn.ftz.f32 %0, %1, %2, %3;" : "=f"(d) : "f"(a), "f"(b), "f"(c)); return d;
}
__device__ __forceinline__ float frcp_approx(float a) {
    float c; asm("rcp.approx.ftz.f32 %0, %1;" : "=f"(c) : "f"(a)); return c;
}

// One scan step; exact R12/R13 op structure (canary 9.786814e-09).
// Branch-free: is_one resolves to FSEL, both reductions always computed.
__device__ __forceinline__ float scan_step(float* __restrict__ c,
                                           const float* __restrict__ v,
                                           bool is_one, int lane,
                                           float* __restrict__ pz_slot)
{
    const float SC_UP = 1.8446744073709552e19f;   // 2^64
    const float SC_DN = 5.421010862427522e-20f;   // 2^-64

    float pz[NSLOT], u[NSLOT];
#pragma unroll
    for (int j = 0; j < NSLOT; ++j) {
        pz[j] = fmul_ftz(c[j], v[j]);
        const float w = fsub_ftz(1.0f, v[j]);
        const float m = is_one ? v[j] : w;        // FSEL, no branch
        u[j] = fmul_ftz(c[j], m);
    }
    float psum = fadd_ftz(fadd_ftz(fadd_ftz(pz[0], pz[1]),
                                   fadd_ftz(pz[2], pz[3])),
                          fadd_ftz(pz[4], pz[5]));
    float nsum = fadd_ftz(fadd_ftz(fadd_ftz(u[0], u[1]),
                                   fadd_ftz(u[2], u[3])),
                          fadd_ftz(u[4], u[5]));
#pragma unroll
    for (int off = 1; off <= 4; off <<= 1) {
        nsum = fadd_ftz(nsum, __shfl_xor_sync(0xffffffffu, nsum, off));
        psum = fadd_ftz(psum, __shfl_xor_sync(0xffffffffu, psum, off));
    }
    if (lane == 0) *pz_slot = psum;

    // branch-free correctly-rounded division (bit-identical to div.rn.ftz
    // on this kernel's domain; verified by the 9.786814e-09 canary)
    const float norm = fmaxf(nsum, 1e-6f);
    float y = frcp_approx(norm);
    y = ffma_ftz(ffma_ftz(-norm, y, 1.0f), y, y);
#pragma unroll
    for (int j = 0; j < NSLOT; ++j) {
        const float a  = fmul_ftz(u[j], SC_UP);
        const float q0 = fmul_ftz(a, y);
        const float r  = ffma_ftz(-norm, q0, a);
        c[j] = fmul_ftz(ffma_ftz(r, y, q0), SC_DN);
    }
    return nsum;
}

extern __shared__ float smem_dyn[];

__global__ __launch_bounds__(WPB * 32, 1)
void spair_obj_kl_kernel(const float* __restrict__ z_pres,
                         const float* __restrict__ z_pres_prob,
                         float* __restrict__ out, int B)
{
    // dynamic smem: T[(HW+1)*KW] | pz[WPB*HW] | cd0[48] | bits[WPB*8]
    float*    s_T   = smem_dyn;
    float*    s_pz  = s_T + (HW + 1) * KW;
    float*    s_cd0 = s_pz + WPB * HW;
    unsigned* s_w   = (unsigned*)(s_cd0 + 48);

    const int tid  = threadIdx.x;
    const int warp = tid >> 5;
    const int lane = tid & 31;
    const int b    = blockIdx.x * WPB + warp;

    // ---- padded v-table ----
    // T[i][KOFF + k] = div.rn.ftz(min(k, 256-i), 256-i) for k >= 0 (unscaled
    // Markstein: correctly rounded for these integer operands);
    //   k <  0  -> 0.0f  (== div.rn.ftz(0, d), the clipped value)
    //   i == 256 row     -> 0.0f (prefetch pad, never consumed)
    for (int e = tid; e < (HW + 1) * KW; e += WPB * 32) {
        const int i = e / KW, k = e - i * KW - KOFF, d = HW - i;
        float val = 0.0f;
        if (i < HW && k > 0) {
            const float fk = (float)(k < d ? k : d), fd = (float)d;
            float y = frcp_approx(fd);
            y = ffma_ftz(ffma_ftz(-fd, y, 1.0f), y, y);
            const float q0 = fmul_ftz(fk, y);
            const float r  = ffma_ftz(-fd, q0, fk);
            val = ffma_ftz(r, y, q0);
        }
        s_T[e] = val;
    }

    // ---- cd0 (warp 0; exact op order of the verified kernels) ----
    if (warp == 0) {
        const float  p_f    = 1.0f / (expf(2.0f) + 1.0f);
        const double base_d = (double)p_f;
        const double omp_d  = 1.0 - base_d;
        float c0 = (float)(omp_d * pow(base_d, (double)lane));
        float c1 = (float)(omp_d * pow(base_d, (double)(lane + 32)));
        if (fabsf(c0) < 1.17549435e-38f) c0 = 0.0f;
        if (fabsf(c1) < 1.17549435e-38f) c1 = 0.0f;
        float acc = fadd_ftz(c0, c1);
#pragma unroll
        for (int off = 16; off; off >>= 1)
            acc = fadd_ftz(acc, __shfl_xor_sync(0xffffffffu, acc, off));
        s_cd0[lane] = fdiv_ftz(c0, acc);
        if (lane + 32 < 48) s_cd0[lane + 32] = fdiv_ftz(c1, acc);
    }

    // ---- sample bits ----
    if (b < B) {
        const float* zp = z_pres + (size_t)b * HW;
        unsigned mybits = 0;
#pragma unroll
        for (int j = 0; j < 8; ++j)
            mybits |= (rintf(zp[32 * j + lane]) > 0.5f) ? (1u << j) : 0u;
#pragma unroll
        for (int j = 0; j < 8; ++j) {
            const unsigned wj = __ballot_sync(0xffffffffu, (mybits >> j) & 1u);
            if (lane == 0) s_w[warp * 8 + j] = wj;
        }
    }
    __syncthreads();
    if (b >= B) return;

    const float* pp  = z_pres_prob + (size_t)b * HW;
    float*       o   = out         + (size_t)b * HW;
    float*       pzb = s_pz + warp * HW;

    const int sbase = (lane & 7) * NSLOT;     // 8-lane group owns all 48 slots
    float c[NSLOT];
#pragma unroll
    for (int j = 0; j < NSLOT; ++j) c[j] = s_cd0[sbase + j];

    // v indexing: v_i[j] = Tb[i*KW - csf_i + j], Tb = &T[0][KOFF + sbase]
    const float* Tb = s_T + KOFF + sbase;
    float v[NSLOT];
#pragma unroll
    for (int j = 0; j < NSLOT; ++j) v[j] = Tb[j];   // step 0, csf = 0

    int toff = 0;                 // running offset i*KW - csf_i
    int i_end = HW;
    unsigned cw = 0;

#pragma unroll 1
    for (int q = 0; q < HW / 4; ++q) {
        if ((q & 7) == 0) cw = s_w[warp * 8 + (q >> 3)];

        float ns;
#pragma unroll
        for (int t = 0; t < 4; ++t) {
            const int  i      = 4 * q + t;
            const bool is_one = cw & 1;
            cw >>= 1;
            toff += KW - (is_one ? 1 : 0);    // offset for step i+1

            // prefetch next step's v: 6 LDS, immediate offsets, zero ALU
            float vn[NSLOT];
            const float* tp = Tb + toff;      // i=255 -> padded zero row 256
#pragma unroll
            for (int j = 0; j < NSLOT; ++j) vn[j] = tp[j];

            ns = scan_step(c, v, is_one, lane, pzb + i);

#pragma unroll
            for (int j = 0; j < NSLOT; ++j) v[j] = vn[j];
        }

        // death is absorbing; zeros self-propagate within the quartet,
        // so checking only the 4th nsum is exact.
        if (ns == 0.0f) { i_end = 4 * q + 4; break; }
    }

    __syncwarp();

    // ---- epilogue: KL for all 256 steps in parallel (p_z = 0 after death) --
#pragma unroll
    for (int j = 0; j < 8; ++j) {
        const int   idx = 32 * j + lane;
        const float pzv = (idx < i_end) ? pzb[idx] : 0.0f;
        const float pr  = pp[idx];
        o[idx] = pr * (logf(pr + EPS) - logf(pzv + EPS))
               + (1.0f - pr) * (logf(1.0f - pr + EPS)
                                - logf((1.0f - pzv) + EPS));
    }
}

extern "C" void kernel_launch(void* const* d_in, const int* in_sizes, int n_in,
                              void* d_out, int out_size)
{
    const float* z_pres      = (const float*)d_in[0];
    const float* z_pres_prob = (const float*)d_in[1];
    float*       out         = (float*)d_out;

    const int B = in_sizes[0] / HW;              // 1024
    const int smem_bytes = ((HW + 1) * KW + WPB * HW + 48 + WPB * 8) * 4;  // ~105 KB
    cudaFuncSetAttribute(spair_obj_kl_kernel,
                         cudaFuncAttributeMaxDynamicSharedMemorySize, smem_bytes);
    spair_obj_kl_kernel<<<(B + WPB - 1) / WPB, WPB * 32, smem_bytes>>>(
        z_pres, z_pres_prob, out, B);
}